// round 14
// baseline (speedup 1.0000x reference)
#include <cuda_runtime.h>
#include <cuda_fp16.h>
#include <math.h>
#include <stdint.h>

// ---------------------------------------------------------------------------
// Problem constants (Falcon new-decoder block)
// ---------------------------------------------------------------------------
#define Bn   2
#define Sn   1024
#define Hn   4096
#define NHn  32
#define NKVn 8
#define HDn  128
#define Gn   4            // NH / NKV
#define QKVn 6144         // (NKV*2 + NH) * HD
#define FFn  16384
#define Mtok (Bn * Sn)    // 2048 tokens

// ---------------------------------------------------------------------------
// Scratch (static __device__ arrays)
// ---------------------------------------------------------------------------
__device__ __align__(256) __half g_a16[Mtok * Hn];      // attn_in fp16
__device__ __align__(256) __half g_m16[Mtok * Hn];      // mlp_in fp16
__device__ __align__(256) __half g_qkvh[Mtok * QKVn];   // qkv fp16 (pre-rope)
__device__ __align__(256) __half g_q16[Bn * NHn * Sn * HDn];   // q (pre-scaled)
__device__ __align__(256) __half g_k16[Bn * NKVn * Sn * HDn];
__device__ __align__(256) __half g_v16[Bn * NKVn * Sn * HDn];
__device__ __align__(256) __half g_c16[Mtok * Hn];      // ctx fp16
__device__ __align__(256) float  g_attn_out[Mtok * Hn];
__device__ __align__(256) __half g_f16[Mtok * FFn];     // gelu(fc) fp16
__device__ __align__(256) __half g_wqkv16[(size_t)Hn * QKVn];
__device__ __align__(256) __half g_wd16[(size_t)Hn * Hn];
__device__ __align__(256) __half g_wfc16[(size_t)Hn * FFn];
__device__ __align__(256) __half g_wo16[(size_t)FFn * Hn];

__device__ __forceinline__ uint32_t smem_u32(const void* p) {
    uint32_t a;
    asm("{ .reg .u64 t; cvta.to.shared.u64 t, %1; cvt.u32.u64 %0, t; }" : "=r"(a) : "l"(p));
    return a;
}

__device__ __forceinline__ void ldsm_x4(uint32_t* r, uint32_t addr) {
    asm volatile("ldmatrix.sync.aligned.m8n8.x4.shared.b16 {%0,%1,%2,%3}, [%4];"
                 : "=r"(r[0]), "=r"(r[1]), "=r"(r[2]), "=r"(r[3]) : "r"(addr));
}
__device__ __forceinline__ void ldsm_x4_t(uint32_t* r, uint32_t addr) {
    asm volatile("ldmatrix.sync.aligned.m8n8.x4.trans.shared.b16 {%0,%1,%2,%3}, [%4];"
                 : "=r"(r[0]), "=r"(r[1]), "=r"(r[2]), "=r"(r[3]) : "r"(addr));
}
__device__ __forceinline__ void mma16816(float* d, const uint32_t* a, uint32_t b0, uint32_t b1) {
    asm volatile("mma.sync.aligned.m16n8k16.row.col.f32.f16.f16.f32 "
                 "{%0,%1,%2,%3}, {%4,%5,%6,%7}, {%8,%9}, {%0,%1,%2,%3};"
                 : "+f"(d[0]), "+f"(d[1]), "+f"(d[2]), "+f"(d[3])
                 : "r"(a[0]), "r"(a[1]), "r"(a[2]), "r"(a[3]), "r"(b0), "r"(b1));
}

// ---------------------------------------------------------------------------
// f32 -> f16 streaming convert
// ---------------------------------------------------------------------------
__global__ void convert_f16_kernel(const float* __restrict__ W, __half* __restrict__ O, long n)
{
    long i = ((long)blockIdx.x * blockDim.x + threadIdx.x) * 8;
    if (i >= n) return;
    float4 v0 = *(const float4*)(W + i);
    float4 v1 = *(const float4*)(W + i + 4);
    __half2 h0 = __floats2half2_rn(v0.x, v0.y);
    __half2 h1 = __floats2half2_rn(v0.z, v0.w);
    __half2 h2 = __floats2half2_rn(v1.x, v1.y);
    __half2 h3 = __floats2half2_rn(v1.z, v1.w);
    uint4 pk = make_uint4(*(uint32_t*)&h0, *(uint32_t*)&h1, *(uint32_t*)&h2, *(uint32_t*)&h3);
    *(uint4*)(O + i) = pk;
}

// ---------------------------------------------------------------------------
// Fused double LayerNorm -> fp16 outputs (shared mean/var)
// ---------------------------------------------------------------------------
__global__ void ln2_kernel(const float* __restrict__ x,
                           const float* __restrict__ sa, const float* __restrict__ ba,
                           const float* __restrict__ sm2, const float* __restrict__ bm2)
{
    const int row = blockIdx.x;
    const float* xr = x + (size_t)row * Hn;
    float s = 0.f, sq = 0.f;
    for (int i = threadIdx.x * 4; i < Hn; i += blockDim.x * 4) {
        float4 v = *(const float4*)(xr + i);
        s  += v.x + v.y + v.z + v.w;
        sq += v.x * v.x + v.y * v.y + v.z * v.z + v.w * v.w;
    }
    for (int o = 16; o > 0; o >>= 1) {
        s  += __shfl_down_sync(0xffffffffu, s, o);
        sq += __shfl_down_sync(0xffffffffu, sq, o);
    }
    __shared__ float rs[8], rq[8];
    __shared__ float s_mean, s_rinv;
    const int lane = threadIdx.x & 31, wid = threadIdx.x >> 5;
    if (lane == 0) { rs[wid] = s; rq[wid] = sq; }
    __syncthreads();
    if (threadIdx.x == 0) {
        float ts = 0.f, tq = 0.f;
        for (int w = 0; w < 8; w++) { ts += rs[w]; tq += rq[w]; }
        float mean = ts * (1.0f / Hn);
        float var  = tq * (1.0f / Hn) - mean * mean;
        s_mean = mean;
        s_rinv = rsqrtf(var + 1e-5f);
    }
    __syncthreads();
    const float mean = s_mean, rinv = s_rinv;
    const size_t rb = (size_t)row * Hn;
    for (int i = threadIdx.x * 4; i < Hn; i += blockDim.x * 4) {
        float4 v  = *(const float4*)(xr + i);
        float4 va = *(const float4*)(sa + i);
        float4 vb = *(const float4*)(ba + i);
        float4 vc = *(const float4*)(sm2 + i);
        float4 vd = *(const float4*)(bm2 + i);
        float4 n;
        n.x = (v.x - mean) * rinv; n.y = (v.y - mean) * rinv;
        n.z = (v.z - mean) * rinv; n.w = (v.w - mean) * rinv;
        __half2 a0 = __floats2half2_rn(n.x * va.x + vb.x, n.y * va.y + vb.y);
        __half2 a1 = __floats2half2_rn(n.z * va.z + vb.z, n.w * va.w + vb.w);
        __half2 m0 = __floats2half2_rn(n.x * vc.x + vd.x, n.y * vc.y + vd.y);
        __half2 m1 = __floats2half2_rn(n.z * vc.z + vd.z, n.w * vc.w + vd.w);
        *(uint2*)(g_a16 + rb + i) = make_uint2(*(uint32_t*)&a0, *(uint32_t*)&a1);
        *(uint2*)(g_m16 + rb + i) = make_uint2(*(uint32_t*)&m0, *(uint32_t*)&m1);
    }
}

// ---------------------------------------------------------------------------
// HMMA fp16 GEMM: BM=128, BN=128, BK=32, 256 threads, 4-stage, 2 CTAs/SM.
// EPI: 0 = fp32 C, 1 = exact GELU -> fp16 C, 2 = C + add1 + add2 -> fp32,
//      4 = plain fp16 C
// ---------------------------------------------------------------------------
#define BMg 128
#define BNg 128
#define BKg 32
#define NSTAGE 4
#define A_STRIDE_B 80
#define B_STRIDE_B 272
#define A_STAGE_B (BMg * A_STRIDE_B)              // 10240
#define B_STAGE_B (BKg * B_STRIDE_B)              // 8704
#define STAGE_B   (A_STAGE_B + B_STAGE_B)         // 18944
#define SMEM_GEMM_TOTAL (NSTAGE * STAGE_B)        // 75776

__device__ __forceinline__ float gelu_exact(float x) {
    return 0.5f * x * (1.0f + erff(x * 0.70710678118654752f));
}

template <int EPI>
__global__ __launch_bounds__(256, 2)
void tc_gemm(const __half* __restrict__ A, const __half* __restrict__ W,
             float* __restrict__ Cf, __half* __restrict__ Ch,
             const float* __restrict__ add1, const float* __restrict__ add2,
             int N, int K)
{
    extern __shared__ char smg[];
    const uint32_t sb = smem_u32(smg);
    const int tid = threadIdx.x;
    const int l   = tid & 31;
    const int wid = tid >> 5;
    const int wm  = wid >> 2;        // 0..1
    const int wn  = wid & 3;         // 0..3
    const int m0  = blockIdx.y * BMg;
    const int n0  = blockIdx.x * BNg;
    const int NC  = K / BKg;

    float acc[4][4][4];
#pragma unroll
    for (int mi = 0; mi < 4; mi++)
#pragma unroll
        for (int nj = 0; nj < 4; nj++)
#pragma unroll
            for (int e = 0; e < 4; e++) acc[mi][nj][e] = 0.f;

    auto issue = [&](int c) {
        if (c < NC) {
            const int k0 = c * BKg;
            const uint32_t st = sb + (uint32_t)(c & (NSTAGE - 1)) * STAGE_B;
#pragma unroll
            for (int i = tid; i < 512; i += 256) {
                const int r = i >> 2, cc = i & 3;
                const __half* gp = A + (size_t)(m0 + r) * K + k0 + cc * 8;
                const uint32_t sp = st + (uint32_t)r * A_STRIDE_B + cc * 16;
                asm volatile("cp.async.cg.shared.global [%0], [%1], 16;" :: "r"(sp), "l"(gp));
            }
#pragma unroll
            for (int i = tid; i < 512; i += 256) {
                const int r = i >> 4, cc = i & 15;
                const __half* gp = W + (size_t)(k0 + r) * N + n0 + cc * 8;
                const uint32_t sp = st + A_STAGE_B + (uint32_t)r * B_STRIDE_B + cc * 16;
                asm volatile("cp.async.cg.shared.global [%0], [%1], 16;" :: "r"(sp), "l"(gp));
            }
        }
        asm volatile("cp.async.commit_group;" ::: "memory");
    };

    issue(0); issue(1); issue(2);

    const int q = l >> 3;
    const int aRow = ((q & 1) << 3) + (l & 7);
    const int aCol = (q >> 1) << 4;
    const int bRow = ((q & 1) << 3) + (l & 7);
    const int bCol = ((q >> 1) << 3) * 2;

    for (int c = 0; c < NC; c++) {
        asm volatile("cp.async.wait_group 2;" ::: "memory");
        __syncthreads();
        issue(c + 3);

        const uint32_t st = sb + (uint32_t)(c & (NSTAGE - 1)) * STAGE_B;
        const uint32_t aB = st;
        const uint32_t bB = st + A_STAGE_B;
#pragma unroll
        for (int ks = 0; ks < 2; ks++) {
            uint32_t Af[4][4];
#pragma unroll
            for (int mi = 0; mi < 4; mi++) {
                const uint32_t addr = aB
                    + (uint32_t)(wm * 64 + mi * 16 + aRow) * A_STRIDE_B
                    + (uint32_t)(ks * 32 + aCol);
                ldsm_x4(Af[mi], addr);
            }
            uint32_t Bf[2][4];
#pragma unroll
            for (int p = 0; p < 2; p++) {
                const uint32_t addr = bB
                    + (uint32_t)(ks * 16 + bRow) * B_STRIDE_B
                    + (uint32_t)((wn * 32 + p * 16) * 2 + bCol);
                ldsm_x4_t(Bf[p], addr);
            }
#pragma unroll
            for (int mi = 0; mi < 4; mi++)
#pragma unroll
                for (int nj = 0; nj < 4; nj++)
                    mma16816(acc[mi][nj], Af[mi], Bf[nj >> 1][(nj & 1) * 2], Bf[nj >> 1][(nj & 1) * 2 + 1]);
        }
    }
    asm volatile("cp.async.wait_group 0;" ::: "memory");

    const int rr = l >> 2;
    const int cc = (l & 3) * 2;
#pragma unroll
    for (int mi = 0; mi < 4; mi++) {
        const int row = m0 + wm * 64 + mi * 16 + rr;
#pragma unroll
        for (int nj = 0; nj < 4; nj++) {
            const int col = n0 + wn * 32 + nj * 8 + cc;
            const size_t i0 = (size_t)row * N + col;
            const size_t i1 = (size_t)(row + 8) * N + col;
            const float* d = acc[mi][nj];
            if (EPI == 0) {
                *(float2*)(Cf + i0) = make_float2(d[0], d[1]);
                *(float2*)(Cf + i1) = make_float2(d[2], d[3]);
            } else if (EPI == 1) {
                __half2 h0 = __floats2half2_rn(gelu_exact(d[0]), gelu_exact(d[1]));
                __half2 h1 = __floats2half2_rn(gelu_exact(d[2]), gelu_exact(d[3]));
                *(uint32_t*)(Ch + i0) = *(uint32_t*)&h0;
                *(uint32_t*)(Ch + i1) = *(uint32_t*)&h1;
            } else if (EPI == 4) {
                __half2 h0 = __floats2half2_rn(d[0], d[1]);
                __half2 h1 = __floats2half2_rn(d[2], d[3]);
                *(uint32_t*)(Ch + i0) = *(uint32_t*)&h0;
                *(uint32_t*)(Ch + i1) = *(uint32_t*)&h1;
            } else {
                float2 a0 = *(const float2*)(add1 + i0);
                float2 b0 = *(const float2*)(add2 + i0);
                float2 a1 = *(const float2*)(add1 + i1);
                float2 b1 = *(const float2*)(add2 + i1);
                *(float2*)(Cf + i0) = make_float2(d[0] + a0.x + b0.x, d[1] + a0.y + b0.y);
                *(float2*)(Cf + i1) = make_float2(d[2] + a1.x + b1.x, d[3] + a1.y + b1.y);
            }
        }
    }
}

// ---------------------------------------------------------------------------
// RoPE + grouped head split (fp16 in -> fp16 q/k/v, q pre-scaled by 1/sqrt(HD))
// ---------------------------------------------------------------------------
__global__ void rope_split_kernel(const float* __restrict__ sin_tab,
                                  const float* __restrict__ cos_tab,
                                  const int* __restrict__ pos_ids)
{
    const long total = (long)Bn * Sn * NKVn * (Gn + 2) * HDn;
    long idx = (long)blockIdx.x * blockDim.x + threadIdx.x;
    if (idx >= total) return;
    const int d    = (int)(idx & (HDn - 1));
    const int slot = (int)((idx >> 7) % (Gn + 2));
    const int kv   = (int)((idx / ((Gn + 2) * HDn)) % NKVn);
    const int s    = (int)((idx / ((long)NKVn * (Gn + 2) * HDn)) % Sn);
    const int b    = (int)(idx / ((long)Sn * NKVn * (Gn + 2) * HDn));

    const float x = __half2float(g_qkvh[idx]);
    if (slot == Gn + 1) {
        g_v16[(((size_t)(b * NKVn + kv) * Sn) + s) * HDn + d] = __float2half_rn(x);
        return;
    }
    const int pos = pos_ids[b * Sn + s];
    const float sn = sin_tab[pos * HDn + d];
    const float cs = cos_tab[pos * HDn + d];
    float xp, val;
    if (d < HDn / 2) {
        xp  = __half2float(g_qkvh[idx + HDn / 2]);
        val = x * cs - xp * sn;
    } else {
        xp  = __half2float(g_qkvh[idx - HDn / 2]);
        val = x * cs + xp * sn;
    }
    if (slot < Gn) {
        const int h = kv * Gn + slot;
        g_q16[(((size_t)(b * NHn + h) * Sn) + s) * HDn + d] =
            __float2half_rn(val * 0.08838834764831845f);
    } else {
        g_k16[(((size_t)(b * NKVn + kv) * Sn) + s) * HDn + d] = __float2half_rn(val);
    }
}

// ---------------------------------------------------------------------------
// HMMA fp16 flash attention, BQ=64 (4 warps x 16 rows), K tile 64 keys.
// Double-buffered cp.async K/V; Q fragments register-resident.
// Longest-first CTA order: qt = gridDim.x-1-bx.
// ---------------------------------------------------------------------------
#define BQ  64
#define SKB 272
#define AQ_B  (64 * SKB)
#define ATTN_Q_OFF  0
#define ATTN_K_OFF  17408
#define ATTN_V_OFF  52224
#define ATTN_MADD_OFF 87040
#define ATTN_SMEM_BYTES (87040 + 2 * 64 * 4)

__global__ __launch_bounds__(128)
void attn_hmma_kernel(const int* __restrict__ amask)
{
    extern __shared__ char sma[];
    const uint32_t sb = smem_u32(sma);
    const uint32_t Qb = sb + ATTN_Q_OFF;
    const uint32_t Kb = sb + ATTN_K_OFF;
    const uint32_t Vb = sb + ATTN_V_OFF;
    float* madd = (float*)(sma + ATTN_MADD_OFF);

    const int t = threadIdx.x;
    const int l = t & 31;
    const int w = t >> 5;
    const int qt = gridDim.x - 1 - blockIdx.x;   // longest-first scheduling
    const int h = blockIdx.y, b = blockIdx.z;
    const int q0 = qt * BQ;
    const int kvh = h >> 2;
    const __half* Qg = g_q16 + (((size_t)(b * NHn + h) * Sn) + q0) * HDn;
    const __half* Kg = g_k16 + ((size_t)(b * NKVn + kvh) * Sn) * HDn;
    const __half* Vg = g_v16 + ((size_t)(b * NKVn + kvh) * Sn) * HDn;
    const int* am = amask + b * Sn;

    const int rsel = l & 15;
    const int csel = l >> 4;
    const int g   = l >> 2;
    const int tq  = l & 3;
    const int wr0 = w * 16;

    for (int i = t; i < 64 * 16; i += 128) {
        const int r = i >> 4, cc = i & 15;
        const uint32_t so = (uint32_t)r * SKB + cc * 16;
        const size_t go = (size_t)r * 256 + cc * 16;
        asm volatile("cp.async.cg.shared.global [%0], [%1], 16;"
                     :: "r"(Qb + so), "l"((const char*)Qg + go));
        asm volatile("cp.async.cg.shared.global [%0], [%1], 16;"
                     :: "r"(Kb + so), "l"((const char*)Kg + go));
        asm volatile("cp.async.cg.shared.global [%0], [%1], 16;"
                     :: "r"(Vb + so), "l"((const char*)Vg + go));
    }
    if (t < 64) madd[t] = (am[t] != 0) ? 0.f : -1e30f;
    asm volatile("cp.async.commit_group;" ::: "memory");

    uint32_t qa[8][4];
    float oacc[16][4];
#pragma unroll
    for (int i = 0; i < 16; i++)
#pragma unroll
        for (int e = 0; e < 4; e++) oacc[i][e] = 0.f;
    float m_lo = -1e30f, m_hi = -1e30f, l_lo = 0.f, l_hi = 0.f;
    const int qlo = q0 + wr0 + g, qhi = qlo + 8;

    for (int kt = 0; kt <= qt; kt++) {
        asm volatile("cp.async.wait_group 0;" ::: "memory");
        __syncthreads();
        const int buf = kt & 1;

        if (kt == 0) {
#pragma unroll
            for (int ks = 0; ks < 8; ks++)
                ldsm_x4(qa[ks], Qb + (uint32_t)(wr0 + rsel) * SKB + ks * 32 + csel * 16);
        }
        if (kt < qt) {
            const int nb = buf ^ 1;
            const size_t gbase = (size_t)(kt + 1) * 64 * 256;
            for (int i = t; i < 64 * 16; i += 128) {
                const int r = i >> 4, cc = i & 15;
                const uint32_t so = (uint32_t)nb * AQ_B + (uint32_t)r * SKB + cc * 16;
                const size_t go = gbase + (size_t)r * 256 + cc * 16;
                asm volatile("cp.async.cg.shared.global [%0], [%1], 16;"
                             :: "r"(Kb + so), "l"((const char*)Kg + go));
                asm volatile("cp.async.cg.shared.global [%0], [%1], 16;"
                             :: "r"(Vb + so), "l"((const char*)Vg + go));
            }
            if (t < 64) madd[nb * 64 + t] = (am[(kt + 1) * 64 + t] != 0) ? 0.f : -1e30f;
            asm volatile("cp.async.commit_group;" ::: "memory");
        }

        const uint32_t kB = Kb + (uint32_t)buf * AQ_B;
        float sa[8][4];
#pragma unroll
        for (int j = 0; j < 8; j++)
#pragma unroll
            for (int e = 0; e < 4; e++) sa[j][e] = 0.f;
#pragma unroll
        for (int ks = 0; ks < 8; ks++) {
            uint32_t kb4[4][4];
#pragma unroll
            for (int np = 0; np < 4; np++)
                ldsm_x4(kb4[np], kB + (uint32_t)(np * 16 + rsel) * SKB + ks * 32 + csel * 16);
#pragma unroll
            for (int np = 0; np < 4; np++) {
                mma16816(sa[2 * np],     qa[ks], kb4[np][0], kb4[np][2]);
                mma16816(sa[2 * np + 1], qa[ks], kb4[np][1], kb4[np][3]);
            }
        }

        const float* md = madd + buf * 64;
        const int kb0 = kt * 64;
        const bool diag = (kt == qt);
        float vlo = -1e30f, vhi = -1e30f;
#pragma unroll
        for (int j = 0; j < 8; j++) {
#pragma unroll
            for (int e = 0; e < 2; e++) {
                const int col = j * 8 + 2 * tq + e;
                const float ad = md[col];
                float xl = sa[j][e] + ad;
                float xh = sa[j][2 + e] + ad;
                if (diag) {
                    if (kb0 + col > qlo) xl = -1e30f;
                    if (kb0 + col > qhi) xh = -1e30f;
                }
                sa[j][e] = xl; sa[j][2 + e] = xh;
                vlo = fmaxf(vlo, xl); vhi = fmaxf(vhi, xh);
            }
        }
        vlo = fmaxf(vlo, __shfl_xor_sync(0xffffffffu, vlo, 1));
        vlo = fmaxf(vlo, __shfl_xor_sync(0xffffffffu, vlo, 2));
        vhi = fmaxf(vhi, __shfl_xor_sync(0xffffffffu, vhi, 1));
        vhi = fmaxf(vhi, __shfl_xor_sync(0xffffffffu, vhi, 2));
        const float mn_lo = fmaxf(m_lo, vlo);
        const float mn_hi = fmaxf(m_hi, vhi);
        const float al_lo = __expf(m_lo - mn_lo);
        const float al_hi = __expf(m_hi - mn_hi);
        float s_lo = 0.f, s_hi = 0.f;
#pragma unroll
        for (int j = 0; j < 8; j++) {
#pragma unroll
            for (int e = 0; e < 2; e++) {
                const float pl = __expf(sa[j][e] - mn_lo);
                const float ph = __expf(sa[j][2 + e] - mn_hi);
                sa[j][e] = pl; sa[j][2 + e] = ph;
                s_lo += pl; s_hi += ph;
            }
        }
        s_lo += __shfl_xor_sync(0xffffffffu, s_lo, 1);
        s_lo += __shfl_xor_sync(0xffffffffu, s_lo, 2);
        s_hi += __shfl_xor_sync(0xffffffffu, s_hi, 1);
        s_hi += __shfl_xor_sync(0xffffffffu, s_hi, 2);
        l_lo = l_lo * al_lo + s_lo;
        l_hi = l_hi * al_hi + s_hi;
        m_lo = mn_lo; m_hi = mn_hi;

#pragma unroll
        for (int i = 0; i < 16; i++) {
            oacc[i][0] *= al_lo; oacc[i][1] *= al_lo;
            oacc[i][2] *= al_hi; oacc[i][3] *= al_hi;
        }
        uint32_t plo[8], phi[8];
#pragma unroll
        for (int j = 0; j < 8; j++) {
            __half2 hl = __floats2half2_rn(sa[j][0], sa[j][1]);
            __half2 hh = __floats2half2_rn(sa[j][2], sa[j][3]);
            plo[j] = *(uint32_t*)&hl; phi[j] = *(uint32_t*)&hh;
        }

        const uint32_t vB = Vb + (uint32_t)buf * AQ_B;
#pragma unroll
        for (int ks2 = 0; ks2 < 4; ks2++) {
            uint32_t A[4] = {plo[2 * ks2], phi[2 * ks2], plo[2 * ks2 + 1], phi[2 * ks2 + 1]};
#pragma unroll
            for (int np = 0; np < 8; np++) {
                uint32_t vb4[4];
                ldsm_x4_t(vb4, vB + (uint32_t)(ks2 * 16 + rsel) * SKB + np * 32 + csel * 16);
                mma16816(oacc[2 * np],     A, vb4[0], vb4[1]);
                mma16816(oacc[2 * np + 1], A, vb4[2], vb4[3]);
            }
        }
        __syncthreads();
    }

    const float inv_lo = 1.0f / l_lo;
    const float inv_hi = 1.0f / l_hi;
    const size_t tok_lo = (size_t)(b * Sn + q0 + wr0 + g);
    const size_t tok_hi = tok_lo + 8;
#pragma unroll
    for (int nt = 0; nt < 16; nt++) {
        const int col = h * HDn + nt * 8 + 2 * tq;
        __half2 lo = __floats2half2_rn(oacc[nt][0] * inv_lo, oacc[nt][1] * inv_lo);
        __half2 hi = __floats2half2_rn(oacc[nt][2] * inv_hi, oacc[nt][3] * inv_hi);
        *(uint32_t*)(g_c16 + tok_lo * Hn + col) = *(uint32_t*)&lo;
        *(uint32_t*)(g_c16 + tok_hi * Hn + col) = *(uint32_t*)&hi;
    }
}

// ---------------------------------------------------------------------------
// Launch (stream-forked DAG; wq convert first on s2, LN first on s0)
// ---------------------------------------------------------------------------
extern "C" void kernel_launch(void* const* d_in, const int* in_sizes, int n_in,
                              void* d_out, int out_size)
{
    (void)in_sizes; (void)n_in; (void)out_size;
    const float* hidden   = (const float*)d_in[0];
    const float* w_qkv    = (const float*)d_in[1];
    const float* w_dense  = (const float*)d_in[2];
    const float* ln_a_s   = (const float*)d_in[3];
    const float* ln_a_b   = (const float*)d_in[4];
    const float* ln_m_s   = (const float*)d_in[5];
    const float* ln_m_b   = (const float*)d_in[6];
    const float* w_fc     = (const float*)d_in[7];
    const float* w_out    = (const float*)d_in[8];
    const float* sin_tab  = (const float*)d_in[9];
    const float* cos_tab  = (const float*)d_in[10];
    const int*   amask    = (const int*)d_in[11];
    const int*   pos_ids  = (const int*)d_in[12];
    float* out = (float*)d_out;

    void *p_a16, *p_m16, *p_qkvh, *p_c16, *p_ao, *p_f16;
    void *p_wq, *p_wd, *p_wf, *p_wo;
    cudaGetSymbolAddress(&p_a16, g_a16);
    cudaGetSymbolAddress(&p_m16, g_m16);
    cudaGetSymbolAddress(&p_qkvh, g_qkvh);
    cudaGetSymbolAddress(&p_c16, g_c16);
    cudaGetSymbolAddress(&p_ao,  g_attn_out);
    cudaGetSymbolAddress(&p_f16, g_f16);
    cudaGetSymbolAddress(&p_wq, g_wqkv16);
    cudaGetSymbolAddress(&p_wd, g_wd16);
    cudaGetSymbolAddress(&p_wf, g_wfc16);
    cudaGetSymbolAddress(&p_wo, g_wo16);

    static cudaStream_t s1 = nullptr, s2 = nullptr;
    static cudaEvent_t evRoot, evLN, evWQ, evWD, evFC, evWO;
    if (s1 == nullptr) {
        cudaStreamCreateWithFlags(&s1, cudaStreamNonBlocking);
        cudaStreamCreateWithFlags(&s2, cudaStreamNonBlocking);
        cudaEventCreateWithFlags(&evRoot, cudaEventDisableTiming);
        cudaEventCreateWithFlags(&evLN,   cudaEventDisableTiming);
        cudaEventCreateWithFlags(&evWQ,   cudaEventDisableTiming);
        cudaEventCreateWithFlags(&evWD,   cudaEventDisableTiming);
        cudaEventCreateWithFlags(&evFC,   cudaEventDisableTiming);
        cudaEventCreateWithFlags(&evWO,   cudaEventDisableTiming);
        cudaFuncSetAttribute(tc_gemm<0>, cudaFuncAttributeMaxDynamicSharedMemorySize, SMEM_GEMM_TOTAL);
        cudaFuncSetAttribute(tc_gemm<1>, cudaFuncAttributeMaxDynamicSharedMemorySize, SMEM_GEMM_TOTAL);
        cudaFuncSetAttribute(tc_gemm<2>, cudaFuncAttributeMaxDynamicSharedMemorySize, SMEM_GEMM_TOTAL);
        cudaFuncSetAttribute(tc_gemm<4>, cudaFuncAttributeMaxDynamicSharedMemorySize, SMEM_GEMM_TOTAL);
        cudaFuncSetAttribute(attn_hmma_kernel, cudaFuncAttributeMaxDynamicSharedMemorySize, ATTN_SMEM_BYTES);
    }

    const long nq = (long)Hn * QKVn, nd = (long)Hn * Hn, nf = (long)Hn * FFn, no = (long)FFn * Hn;

    // fork side streams off the captured origin stream
    cudaEventRecord(evRoot, 0);
    cudaStreamWaitEvent(s1, evRoot, 0);
    cudaStreamWaitEvent(s2, evRoot, 0);

    // s2: qkv + dense + out weight converts (qkv first — needed earliest)
    convert_f16_kernel<<<(int)(nq / (256 * 8)), 256, 0, s2>>>(w_qkv, (__half*)p_wq, nq);
    cudaEventRecord(evWQ, s2);
    convert_f16_kernel<<<(int)(nd / (256 * 8)), 256, 0, s2>>>(w_dense, (__half*)p_wd, nd);
    cudaEventRecord(evWD, s2);
    convert_f16_kernel<<<(int)(no / (256 * 8)), 256, 0, s2>>>(w_out, (__half*)p_wo, no);
    cudaEventRecord(evWO, s2);

    // s1: fc weight convert (fc gemm waits on LN)
    convert_f16_kernel<<<(int)(nf / (256 * 8)), 256, 0, s1>>>(w_fc, (__half*)p_wf, nf);

    // s0: double layernorm immediately (gates both branches)
    ln2_kernel<<<Mtok, 256>>>(hidden, ln_a_s, ln_a_b, ln_m_s, ln_m_b);
    cudaEventRecord(evLN, 0);

    // s1 branch: MLP fc + GELU (overlaps the whole attention branch on s0)
    cudaStreamWaitEvent(s1, evLN, 0);
    tc_gemm<1><<<dim3(FFn / BNg, Mtok / BMg), 256, SMEM_GEMM_TOTAL, s1>>>(
        (const __half*)p_m16, (const __half*)p_wf,
        nullptr, (__half*)p_f16, nullptr, nullptr, FFn, Hn);
    cudaEventRecord(evFC, s1);

    // s0 branch: attention chain (qkv gemm -> fp16, rope, attn, dense)
    cudaStreamWaitEvent(0, evWQ, 0);
    tc_gemm<4><<<dim3(QKVn / BNg, Mtok / BMg), 256, SMEM_GEMM_TOTAL>>>(
        (const __half*)p_a16, (const __half*)p_wq,
        nullptr, (__half*)p_qkvh, nullptr, nullptr, QKVn, Hn);
    {
        const long total = (long)Bn * Sn * NKVn * (Gn + 2) * HDn;
        rope_split_kernel<<<(int)((total + 255) / 256), 256>>>(sin_tab, cos_tab, pos_ids);
    }
    attn_hmma_kernel<<<dim3(Sn / BQ, NHn, Bn), 128, ATTN_SMEM_BYTES>>>(amask);

    cudaStreamWaitEvent(0, evWD, 0);
    tc_gemm<0><<<dim3(Hn / BNg, Mtok / BMg), 256, SMEM_GEMM_TOTAL>>>(
        (const __half*)p_c16, (const __half*)p_wd,
        (float*)p_ao, nullptr, nullptr, nullptr, Hn, Hn);

    // join: out gemm needs fc (s1), wo (s2), attn_out + hidden (s0)
    cudaStreamWaitEvent(0, evFC, 0);
    cudaStreamWaitEvent(0, evWO, 0);
    tc_gemm<2><<<dim3(Hn / BNg, Mtok / BMg), 256, SMEM_GEMM_TOTAL>>>(
        (const __half*)p_f16, (const __half*)p_wo,
        out, nullptr, hidden, (const float*)p_ao, Hn, FFn);
}

// round 15
// speedup vs baseline: 1.0017x; 1.0017x over previous
#include <cuda_runtime.h>
#include <cuda_fp16.h>
#include <math.h>
#include <stdint.h>

// ---------------------------------------------------------------------------
// Problem constants (Falcon new-decoder block)
// ---------------------------------------------------------------------------
#define Bn   2
#define Sn   1024
#define Hn   4096
#define NHn  32
#define NKVn 8
#define HDn  128
#define Gn   4            // NH / NKV
#define QKVn 6144         // (NKV*2 + NH) * HD
#define FFn  16384
#define Mtok (Bn * Sn)    // 2048 tokens

// ---------------------------------------------------------------------------
// Scratch (static __device__ arrays)
// ---------------------------------------------------------------------------
__device__ __align__(256) __half g_a16[Mtok * Hn];      // attn_in fp16
__device__ __align__(256) __half g_m16[Mtok * Hn];      // mlp_in fp16
__device__ __align__(256) __half g_qkvh[Mtok * QKVn];   // qkv fp16 (pre-rope)
__device__ __align__(256) __half g_q16[Bn * NHn * Sn * HDn];   // q (pre-scaled)
__device__ __align__(256) __half g_k16[Bn * NKVn * Sn * HDn];
__device__ __align__(256) __half g_v16[Bn * NKVn * Sn * HDn];
__device__ __align__(256) __half g_c16[Mtok * Hn];      // ctx fp16
__device__ __align__(256) float  g_attn_out[Mtok * Hn];
__device__ __align__(256) __half g_f16[Mtok * FFn];     // gelu(fc) fp16
__device__ __align__(256) __half g_wqkv16[(size_t)Hn * QKVn];
__device__ __align__(256) __half g_wd16[(size_t)Hn * Hn];
__device__ __align__(256) __half g_wfc16[(size_t)Hn * FFn];
__device__ __align__(256) __half g_wo16[(size_t)FFn * Hn];

__device__ __forceinline__ uint32_t smem_u32(const void* p) {
    uint32_t a;
    asm("{ .reg .u64 t; cvta.to.shared.u64 t, %1; cvt.u32.u64 %0, t; }" : "=r"(a) : "l"(p));
    return a;
}

__device__ __forceinline__ void ldsm_x4(uint32_t* r, uint32_t addr) {
    asm volatile("ldmatrix.sync.aligned.m8n8.x4.shared.b16 {%0,%1,%2,%3}, [%4];"
                 : "=r"(r[0]), "=r"(r[1]), "=r"(r[2]), "=r"(r[3]) : "r"(addr));
}
__device__ __forceinline__ void ldsm_x4_t(uint32_t* r, uint32_t addr) {
    asm volatile("ldmatrix.sync.aligned.m8n8.x4.trans.shared.b16 {%0,%1,%2,%3}, [%4];"
                 : "=r"(r[0]), "=r"(r[1]), "=r"(r[2]), "=r"(r[3]) : "r"(addr));
}
__device__ __forceinline__ void mma16816(float* d, const uint32_t* a, uint32_t b0, uint32_t b1) {
    asm volatile("mma.sync.aligned.m16n8k16.row.col.f32.f16.f16.f32 "
                 "{%0,%1,%2,%3}, {%4,%5,%6,%7}, {%8,%9}, {%0,%1,%2,%3};"
                 : "+f"(d[0]), "+f"(d[1]), "+f"(d[2]), "+f"(d[3])
                 : "r"(a[0]), "r"(a[1]), "r"(a[2]), "r"(a[3]), "r"(b0), "r"(b1));
}

// ---------------------------------------------------------------------------
// f32 -> f16 streaming convert
// ---------------------------------------------------------------------------
__global__ void convert_f16_kernel(const float* __restrict__ W, __half* __restrict__ O, long n)
{
    long i = ((long)blockIdx.x * blockDim.x + threadIdx.x) * 8;
    if (i >= n) return;
    float4 v0 = *(const float4*)(W + i);
    float4 v1 = *(const float4*)(W + i + 4);
    __half2 h0 = __floats2half2_rn(v0.x, v0.y);
    __half2 h1 = __floats2half2_rn(v0.z, v0.w);
    __half2 h2 = __floats2half2_rn(v1.x, v1.y);
    __half2 h3 = __floats2half2_rn(v1.z, v1.w);
    uint4 pk = make_uint4(*(uint32_t*)&h0, *(uint32_t*)&h1, *(uint32_t*)&h2, *(uint32_t*)&h3);
    *(uint4*)(O + i) = pk;
}

// ---------------------------------------------------------------------------
// Fused double LayerNorm -> fp16 outputs (shared mean/var)
// ---------------------------------------------------------------------------
__global__ void ln2_kernel(const float* __restrict__ x,
                           const float* __restrict__ sa, const float* __restrict__ ba,
                           const float* __restrict__ sm2, const float* __restrict__ bm2)
{
    const int row = blockIdx.x;
    const float* xr = x + (size_t)row * Hn;
    float s = 0.f, sq = 0.f;
    for (int i = threadIdx.x * 4; i < Hn; i += blockDim.x * 4) {
        float4 v = *(const float4*)(xr + i);
        s  += v.x + v.y + v.z + v.w;
        sq += v.x * v.x + v.y * v.y + v.z * v.z + v.w * v.w;
    }
    for (int o = 16; o > 0; o >>= 1) {
        s  += __shfl_down_sync(0xffffffffu, s, o);
        sq += __shfl_down_sync(0xffffffffu, sq, o);
    }
    __shared__ float rs[8], rq[8];
    __shared__ float s_mean, s_rinv;
    const int lane = threadIdx.x & 31, wid = threadIdx.x >> 5;
    if (lane == 0) { rs[wid] = s; rq[wid] = sq; }
    __syncthreads();
    if (threadIdx.x == 0) {
        float ts = 0.f, tq = 0.f;
        for (int w = 0; w < 8; w++) { ts += rs[w]; tq += rq[w]; }
        float mean = ts * (1.0f / Hn);
        float var  = tq * (1.0f / Hn) - mean * mean;
        s_mean = mean;
        s_rinv = rsqrtf(var + 1e-5f);
    }
    __syncthreads();
    const float mean = s_mean, rinv = s_rinv;
    const size_t rb = (size_t)row * Hn;
    for (int i = threadIdx.x * 4; i < Hn; i += blockDim.x * 4) {
        float4 v  = *(const float4*)(xr + i);
        float4 va = *(const float4*)(sa + i);
        float4 vb = *(const float4*)(ba + i);
        float4 vc = *(const float4*)(sm2 + i);
        float4 vd = *(const float4*)(bm2 + i);
        float4 n;
        n.x = (v.x - mean) * rinv; n.y = (v.y - mean) * rinv;
        n.z = (v.z - mean) * rinv; n.w = (v.w - mean) * rinv;
        __half2 a0 = __floats2half2_rn(n.x * va.x + vb.x, n.y * va.y + vb.y);
        __half2 a1 = __floats2half2_rn(n.z * va.z + vb.z, n.w * va.w + vb.w);
        __half2 m0 = __floats2half2_rn(n.x * vc.x + vd.x, n.y * vc.y + vd.y);
        __half2 m1 = __floats2half2_rn(n.z * vc.z + vd.z, n.w * vc.w + vd.w);
        *(uint2*)(g_a16 + rb + i) = make_uint2(*(uint32_t*)&a0, *(uint32_t*)&a1);
        *(uint2*)(g_m16 + rb + i) = make_uint2(*(uint32_t*)&m0, *(uint32_t*)&m1);
    }
}

// ---------------------------------------------------------------------------
// HMMA fp16 GEMM: BM=128, BN=128, BK=32, 256 threads, 4-stage, 2 CTAs/SM.
// EPI: 0 = fp32 C, 1 = exact GELU -> fp16 C, 2 = C + add1 + add2 -> fp32,
//      4 = plain fp16 C
// ---------------------------------------------------------------------------
#define BMg 128
#define BNg 128
#define BKg 32
#define NSTAGE 4
#define A_STRIDE_B 80
#define B_STRIDE_B 272
#define A_STAGE_B (BMg * A_STRIDE_B)              // 10240
#define B_STAGE_B (BKg * B_STRIDE_B)              // 8704
#define STAGE_B   (A_STAGE_B + B_STAGE_B)         // 18944
#define SMEM_GEMM_TOTAL (NSTAGE * STAGE_B)        // 75776

__device__ __forceinline__ float gelu_exact(float x) {
    return 0.5f * x * (1.0f + erff(x * 0.70710678118654752f));
}

template <int EPI>
__global__ __launch_bounds__(256, 2)
void tc_gemm(const __half* __restrict__ A, const __half* __restrict__ W,
             float* __restrict__ Cf, __half* __restrict__ Ch,
             const float* __restrict__ add1, const float* __restrict__ add2,
             int N, int K)
{
    extern __shared__ char smg[];
    const uint32_t sb = smem_u32(smg);
    const int tid = threadIdx.x;
    const int l   = tid & 31;
    const int wid = tid >> 5;
    const int wm  = wid >> 2;        // 0..1
    const int wn  = wid & 3;         // 0..3
    const int m0  = blockIdx.y * BMg;
    const int n0  = blockIdx.x * BNg;
    const int NC  = K / BKg;

    float acc[4][4][4];
#pragma unroll
    for (int mi = 0; mi < 4; mi++)
#pragma unroll
        for (int nj = 0; nj < 4; nj++)
#pragma unroll
            for (int e = 0; e < 4; e++) acc[mi][nj][e] = 0.f;

    auto issue = [&](int c) {
        if (c < NC) {
            const int k0 = c * BKg;
            const uint32_t st = sb + (uint32_t)(c & (NSTAGE - 1)) * STAGE_B;
#pragma unroll
            for (int i = tid; i < 512; i += 256) {
                const int r = i >> 2, cc = i & 3;
                const __half* gp = A + (size_t)(m0 + r) * K + k0 + cc * 8;
                const uint32_t sp = st + (uint32_t)r * A_STRIDE_B + cc * 16;
                asm volatile("cp.async.cg.shared.global [%0], [%1], 16;" :: "r"(sp), "l"(gp));
            }
#pragma unroll
            for (int i = tid; i < 512; i += 256) {
                const int r = i >> 4, cc = i & 15;
                const __half* gp = W + (size_t)(k0 + r) * N + n0 + cc * 8;
                const uint32_t sp = st + A_STAGE_B + (uint32_t)r * B_STRIDE_B + cc * 16;
                asm volatile("cp.async.cg.shared.global [%0], [%1], 16;" :: "r"(sp), "l"(gp));
            }
        }
        asm volatile("cp.async.commit_group;" ::: "memory");
    };

    issue(0); issue(1); issue(2);

    const int q = l >> 3;
    const int aRow = ((q & 1) << 3) + (l & 7);
    const int aCol = (q >> 1) << 4;
    const int bRow = ((q & 1) << 3) + (l & 7);
    const int bCol = ((q >> 1) << 3) * 2;

    for (int c = 0; c < NC; c++) {
        asm volatile("cp.async.wait_group 2;" ::: "memory");
        __syncthreads();
        issue(c + 3);

        const uint32_t st = sb + (uint32_t)(c & (NSTAGE - 1)) * STAGE_B;
        const uint32_t aB = st;
        const uint32_t bB = st + A_STAGE_B;
#pragma unroll
        for (int ks = 0; ks < 2; ks++) {
            uint32_t Af[4][4];
#pragma unroll
            for (int mi = 0; mi < 4; mi++) {
                const uint32_t addr = aB
                    + (uint32_t)(wm * 64 + mi * 16 + aRow) * A_STRIDE_B
                    + (uint32_t)(ks * 32 + aCol);
                ldsm_x4(Af[mi], addr);
            }
            uint32_t Bf[2][4];
#pragma unroll
            for (int p = 0; p < 2; p++) {
                const uint32_t addr = bB
                    + (uint32_t)(ks * 16 + bRow) * B_STRIDE_B
                    + (uint32_t)((wn * 32 + p * 16) * 2 + bCol);
                ldsm_x4_t(Bf[p], addr);
            }
#pragma unroll
            for (int mi = 0; mi < 4; mi++)
#pragma unroll
                for (int nj = 0; nj < 4; nj++)
                    mma16816(acc[mi][nj], Af[mi], Bf[nj >> 1][(nj & 1) * 2], Bf[nj >> 1][(nj & 1) * 2 + 1]);
        }
    }
    asm volatile("cp.async.wait_group 0;" ::: "memory");

    const int rr = l >> 2;
    const int cc = (l & 3) * 2;
#pragma unroll
    for (int mi = 0; mi < 4; mi++) {
        const int row = m0 + wm * 64 + mi * 16 + rr;
#pragma unroll
        for (int nj = 0; nj < 4; nj++) {
            const int col = n0 + wn * 32 + nj * 8 + cc;
            const size_t i0 = (size_t)row * N + col;
            const size_t i1 = (size_t)(row + 8) * N + col;
            const float* d = acc[mi][nj];
            if (EPI == 0) {
                *(float2*)(Cf + i0) = make_float2(d[0], d[1]);
                *(float2*)(Cf + i1) = make_float2(d[2], d[3]);
            } else if (EPI == 1) {
                __half2 h0 = __floats2half2_rn(gelu_exact(d[0]), gelu_exact(d[1]));
                __half2 h1 = __floats2half2_rn(gelu_exact(d[2]), gelu_exact(d[3]));
                *(uint32_t*)(Ch + i0) = *(uint32_t*)&h0;
                *(uint32_t*)(Ch + i1) = *(uint32_t*)&h1;
            } else if (EPI == 4) {
                __half2 h0 = __floats2half2_rn(d[0], d[1]);
                __half2 h1 = __floats2half2_rn(d[2], d[3]);
                *(uint32_t*)(Ch + i0) = *(uint32_t*)&h0;
                *(uint32_t*)(Ch + i1) = *(uint32_t*)&h1;
            } else {
                float2 a0 = *(const float2*)(add1 + i0);
                float2 b0 = *(const float2*)(add2 + i0);
                float2 a1 = *(const float2*)(add1 + i1);
                float2 b1 = *(const float2*)(add2 + i1);
                *(float2*)(Cf + i0) = make_float2(d[0] + a0.x + b0.x, d[1] + a0.y + b0.y);
                *(float2*)(Cf + i1) = make_float2(d[2] + a1.x + b1.x, d[3] + a1.y + b1.y);
            }
        }
    }
}

// ---------------------------------------------------------------------------
// RoPE + grouped head split (fp16 in -> fp16 q/k/v, q pre-scaled by 1/sqrt(HD))
// ---------------------------------------------------------------------------
__global__ void rope_split_kernel(const float* __restrict__ sin_tab,
                                  const float* __restrict__ cos_tab,
                                  const int* __restrict__ pos_ids)
{
    const long total = (long)Bn * Sn * NKVn * (Gn + 2) * HDn;
    long idx = (long)blockIdx.x * blockDim.x + threadIdx.x;
    if (idx >= total) return;
    const int d    = (int)(idx & (HDn - 1));
    const int slot = (int)((idx >> 7) % (Gn + 2));
    const int kv   = (int)((idx / ((Gn + 2) * HDn)) % NKVn);
    const int s    = (int)((idx / ((long)NKVn * (Gn + 2) * HDn)) % Sn);
    const int b    = (int)(idx / ((long)Sn * NKVn * (Gn + 2) * HDn));

    const float x = __half2float(g_qkvh[idx]);
    if (slot == Gn + 1) {
        g_v16[(((size_t)(b * NKVn + kv) * Sn) + s) * HDn + d] = __float2half_rn(x);
        return;
    }
    const int pos = pos_ids[b * Sn + s];
    const float sn = sin_tab[pos * HDn + d];
    const float cs = cos_tab[pos * HDn + d];
    float xp, val;
    if (d < HDn / 2) {
        xp  = __half2float(g_qkvh[idx + HDn / 2]);
        val = x * cs - xp * sn;
    } else {
        xp  = __half2float(g_qkvh[idx - HDn / 2]);
        val = x * cs + xp * sn;
    }
    if (slot < Gn) {
        const int h = kv * Gn + slot;
        g_q16[(((size_t)(b * NHn + h) * Sn) + s) * HDn + d] =
            __float2half_rn(val * 0.08838834764831845f);
    } else {
        g_k16[(((size_t)(b * NKVn + kv) * Sn) + s) * HDn + d] = __float2half_rn(val);
    }
}

// ---------------------------------------------------------------------------
// HMMA fp16 flash attention, BQ=64 (4 warps x 16 rows), K tile 64 keys.
// Double-buffered cp.async K/V; Q fragments register-resident.
// Longest-first CTA order: qt = gridDim.x-1-bx.
// ---------------------------------------------------------------------------
#define BQ  64
#define SKB 272
#define AQ_B  (64 * SKB)
#define ATTN_Q_OFF  0
#define ATTN_K_OFF  17408
#define ATTN_V_OFF  52224
#define ATTN_MADD_OFF 87040
#define ATTN_SMEM_BYTES (87040 + 2 * 64 * 4)

__global__ __launch_bounds__(128)
void attn_hmma_kernel(const int* __restrict__ amask)
{
    extern __shared__ char sma[];
    const uint32_t sb = smem_u32(sma);
    const uint32_t Qb = sb + ATTN_Q_OFF;
    const uint32_t Kb = sb + ATTN_K_OFF;
    const uint32_t Vb = sb + ATTN_V_OFF;
    float* madd = (float*)(sma + ATTN_MADD_OFF);

    const int t = threadIdx.x;
    const int l = t & 31;
    const int w = t >> 5;
    const int qt = gridDim.x - 1 - blockIdx.x;   // longest-first scheduling
    const int h = blockIdx.y, b = blockIdx.z;
    const int q0 = qt * BQ;
    const int kvh = h >> 2;
    const __half* Qg = g_q16 + (((size_t)(b * NHn + h) * Sn) + q0) * HDn;
    const __half* Kg = g_k16 + ((size_t)(b * NKVn + kvh) * Sn) * HDn;
    const __half* Vg = g_v16 + ((size_t)(b * NKVn + kvh) * Sn) * HDn;
    const int* am = amask + b * Sn;

    const int rsel = l & 15;
    const int csel = l >> 4;
    const int g   = l >> 2;
    const int tq  = l & 3;
    const int wr0 = w * 16;

    for (int i = t; i < 64 * 16; i += 128) {
        const int r = i >> 4, cc = i & 15;
        const uint32_t so = (uint32_t)r * SKB + cc * 16;
        const size_t go = (size_t)r * 256 + cc * 16;
        asm volatile("cp.async.cg.shared.global [%0], [%1], 16;"
                     :: "r"(Qb + so), "l"((const char*)Qg + go));
        asm volatile("cp.async.cg.shared.global [%0], [%1], 16;"
                     :: "r"(Kb + so), "l"((const char*)Kg + go));
        asm volatile("cp.async.cg.shared.global [%0], [%1], 16;"
                     :: "r"(Vb + so), "l"((const char*)Vg + go));
    }
    if (t < 64) madd[t] = (am[t] != 0) ? 0.f : -1e30f;
    asm volatile("cp.async.commit_group;" ::: "memory");

    uint32_t qa[8][4];
    float oacc[16][4];
#pragma unroll
    for (int i = 0; i < 16; i++)
#pragma unroll
        for (int e = 0; e < 4; e++) oacc[i][e] = 0.f;
    float m_lo = -1e30f, m_hi = -1e30f, l_lo = 0.f, l_hi = 0.f;
    const int qlo = q0 + wr0 + g, qhi = qlo + 8;

    for (int kt = 0; kt <= qt; kt++) {
        asm volatile("cp.async.wait_group 0;" ::: "memory");
        __syncthreads();
        const int buf = kt & 1;

        if (kt == 0) {
#pragma unroll
            for (int ks = 0; ks < 8; ks++)
                ldsm_x4(qa[ks], Qb + (uint32_t)(wr0 + rsel) * SKB + ks * 32 + csel * 16);
        }
        if (kt < qt) {
            const int nb = buf ^ 1;
            const size_t gbase = (size_t)(kt + 1) * 64 * 256;
            for (int i = t; i < 64 * 16; i += 128) {
                const int r = i >> 4, cc = i & 15;
                const uint32_t so = (uint32_t)nb * AQ_B + (uint32_t)r * SKB + cc * 16;
                const size_t go = gbase + (size_t)r * 256 + cc * 16;
                asm volatile("cp.async.cg.shared.global [%0], [%1], 16;"
                             :: "r"(Kb + so), "l"((const char*)Kg + go));
                asm volatile("cp.async.cg.shared.global [%0], [%1], 16;"
                             :: "r"(Vb + so), "l"((const char*)Vg + go));
            }
            if (t < 64) madd[nb * 64 + t] = (am[(kt + 1) * 64 + t] != 0) ? 0.f : -1e30f;
            asm volatile("cp.async.commit_group;" ::: "memory");
        }

        const uint32_t kB = Kb + (uint32_t)buf * AQ_B;
        float sa[8][4];
#pragma unroll
        for (int j = 0; j < 8; j++)
#pragma unroll
            for (int e = 0; e < 4; e++) sa[j][e] = 0.f;
#pragma unroll
        for (int ks = 0; ks < 8; ks++) {
            uint32_t kb4[4][4];
#pragma unroll
            for (int np = 0; np < 4; np++)
                ldsm_x4(kb4[np], kB + (uint32_t)(np * 16 + rsel) * SKB + ks * 32 + csel * 16);
#pragma unroll
            for (int np = 0; np < 4; np++) {
                mma16816(sa[2 * np],     qa[ks], kb4[np][0], kb4[np][2]);
                mma16816(sa[2 * np + 1], qa[ks], kb4[np][1], kb4[np][3]);
            }
        }

        const float* md = madd + buf * 64;
        const int kb0 = kt * 64;
        const bool diag = (kt == qt);
        float vlo = -1e30f, vhi = -1e30f;
#pragma unroll
        for (int j = 0; j < 8; j++) {
#pragma unroll
            for (int e = 0; e < 2; e++) {
                const int col = j * 8 + 2 * tq + e;
                const float ad = md[col];
                float xl = sa[j][e] + ad;
                float xh = sa[j][2 + e] + ad;
                if (diag) {
                    if (kb0 + col > qlo) xl = -1e30f;
                    if (kb0 + col > qhi) xh = -1e30f;
                }
                sa[j][e] = xl; sa[j][2 + e] = xh;
                vlo = fmaxf(vlo, xl); vhi = fmaxf(vhi, xh);
            }
        }
        vlo = fmaxf(vlo, __shfl_xor_sync(0xffffffffu, vlo, 1));
        vlo = fmaxf(vlo, __shfl_xor_sync(0xffffffffu, vlo, 2));
        vhi = fmaxf(vhi, __shfl_xor_sync(0xffffffffu, vhi, 1));
        vhi = fmaxf(vhi, __shfl_xor_sync(0xffffffffu, vhi, 2));
        const float mn_lo = fmaxf(m_lo, vlo);
        const float mn_hi = fmaxf(m_hi, vhi);
        const float al_lo = __expf(m_lo - mn_lo);
        const float al_hi = __expf(m_hi - mn_hi);
        float s_lo = 0.f, s_hi = 0.f;
#pragma unroll
        for (int j = 0; j < 8; j++) {
#pragma unroll
            for (int e = 0; e < 2; e++) {
                const float pl = __expf(sa[j][e] - mn_lo);
                const float ph = __expf(sa[j][2 + e] - mn_hi);
                sa[j][e] = pl; sa[j][2 + e] = ph;
                s_lo += pl; s_hi += ph;
            }
        }
        s_lo += __shfl_xor_sync(0xffffffffu, s_lo, 1);
        s_lo += __shfl_xor_sync(0xffffffffu, s_lo, 2);
        s_hi += __shfl_xor_sync(0xffffffffu, s_hi, 1);
        s_hi += __shfl_xor_sync(0xffffffffu, s_hi, 2);
        l_lo = l_lo * al_lo + s_lo;
        l_hi = l_hi * al_hi + s_hi;
        m_lo = mn_lo; m_hi = mn_hi;

#pragma unroll
        for (int i = 0; i < 16; i++) {
            oacc[i][0] *= al_lo; oacc[i][1] *= al_lo;
            oacc[i][2] *= al_hi; oacc[i][3] *= al_hi;
        }
        uint32_t plo[8], phi[8];
#pragma unroll
        for (int j = 0; j < 8; j++) {
            __half2 hl = __floats2half2_rn(sa[j][0], sa[j][1]);
            __half2 hh = __floats2half2_rn(sa[j][2], sa[j][3]);
            plo[j] = *(uint32_t*)&hl; phi[j] = *(uint32_t*)&hh;
        }

        const uint32_t vB = Vb + (uint32_t)buf * AQ_B;
#pragma unroll
        for (int ks2 = 0; ks2 < 4; ks2++) {
            uint32_t A[4] = {plo[2 * ks2], phi[2 * ks2], plo[2 * ks2 + 1], phi[2 * ks2 + 1]};
#pragma unroll
            for (int np = 0; np < 8; np++) {
                uint32_t vb4[4];
                ldsm_x4_t(vb4, vB + (uint32_t)(ks2 * 16 + rsel) * SKB + np * 32 + csel * 16);
                mma16816(oacc[2 * np],     A, vb4[0], vb4[1]);
                mma16816(oacc[2 * np + 1], A, vb4[2], vb4[3]);
            }
        }
        __syncthreads();
    }

    const float inv_lo = 1.0f / l_lo;
    const float inv_hi = 1.0f / l_hi;
    const size_t tok_lo = (size_t)(b * Sn + q0 + wr0 + g);
    const size_t tok_hi = tok_lo + 8;
#pragma unroll
    for (int nt = 0; nt < 16; nt++) {
        const int col = h * HDn + nt * 8 + 2 * tq;
        __half2 lo = __floats2half2_rn(oacc[nt][0] * inv_lo, oacc[nt][1] * inv_lo);
        __half2 hi = __floats2half2_rn(oacc[nt][2] * inv_hi, oacc[nt][3] * inv_hi);
        *(uint32_t*)(g_c16 + tok_lo * Hn + col) = *(uint32_t*)&lo;
        *(uint32_t*)(g_c16 + tok_hi * Hn + col) = *(uint32_t*)&hi;
    }
}

// ---------------------------------------------------------------------------
// Launch (stream-forked DAG; wq convert first on s2, LN first on s0)
// ---------------------------------------------------------------------------
extern "C" void kernel_launch(void* const* d_in, const int* in_sizes, int n_in,
                              void* d_out, int out_size)
{
    (void)in_sizes; (void)n_in; (void)out_size;
    const float* hidden   = (const float*)d_in[0];
    const float* w_qkv    = (const float*)d_in[1];
    const float* w_dense  = (const float*)d_in[2];
    const float* ln_a_s   = (const float*)d_in[3];
    const float* ln_a_b   = (const float*)d_in[4];
    const float* ln_m_s   = (const float*)d_in[5];
    const float* ln_m_b   = (const float*)d_in[6];
    const float* w_fc     = (const float*)d_in[7];
    const float* w_out    = (const float*)d_in[8];
    const float* sin_tab  = (const float*)d_in[9];
    const float* cos_tab  = (const float*)d_in[10];
    const int*   amask    = (const int*)d_in[11];
    const int*   pos_ids  = (const int*)d_in[12];
    float* out = (float*)d_out;

    void *p_a16, *p_m16, *p_qkvh, *p_c16, *p_ao, *p_f16;
    void *p_wq, *p_wd, *p_wf, *p_wo;
    cudaGetSymbolAddress(&p_a16, g_a16);
    cudaGetSymbolAddress(&p_m16, g_m16);
    cudaGetSymbolAddress(&p_qkvh, g_qkvh);
    cudaGetSymbolAddress(&p_c16, g_c16);
    cudaGetSymbolAddress(&p_ao,  g_attn_out);
    cudaGetSymbolAddress(&p_f16, g_f16);
    cudaGetSymbolAddress(&p_wq, g_wqkv16);
    cudaGetSymbolAddress(&p_wd, g_wd16);
    cudaGetSymbolAddress(&p_wf, g_wfc16);
    cudaGetSymbolAddress(&p_wo, g_wo16);

    static cudaStream_t s1 = nullptr, s2 = nullptr;
    static cudaEvent_t evRoot, evLN, evWQ, evWD, evFC, evWO;
    if (s1 == nullptr) {
        cudaStreamCreateWithFlags(&s1, cudaStreamNonBlocking);
        cudaStreamCreateWithFlags(&s2, cudaStreamNonBlocking);
        cudaEventCreateWithFlags(&evRoot, cudaEventDisableTiming);
        cudaEventCreateWithFlags(&evLN,   cudaEventDisableTiming);
        cudaEventCreateWithFlags(&evWQ,   cudaEventDisableTiming);
        cudaEventCreateWithFlags(&evWD,   cudaEventDisableTiming);
        cudaEventCreateWithFlags(&evFC,   cudaEventDisableTiming);
        cudaEventCreateWithFlags(&evWO,   cudaEventDisableTiming);
        cudaFuncSetAttribute(tc_gemm<0>, cudaFuncAttributeMaxDynamicSharedMemorySize, SMEM_GEMM_TOTAL);
        cudaFuncSetAttribute(tc_gemm<1>, cudaFuncAttributeMaxDynamicSharedMemorySize, SMEM_GEMM_TOTAL);
        cudaFuncSetAttribute(tc_gemm<2>, cudaFuncAttributeMaxDynamicSharedMemorySize, SMEM_GEMM_TOTAL);
        cudaFuncSetAttribute(tc_gemm<4>, cudaFuncAttributeMaxDynamicSharedMemorySize, SMEM_GEMM_TOTAL);
        cudaFuncSetAttribute(attn_hmma_kernel, cudaFuncAttributeMaxDynamicSharedMemorySize, ATTN_SMEM_BYTES);
    }

    const long nq = (long)Hn * QKVn, nd = (long)Hn * Hn, nf = (long)Hn * FFn, no = (long)FFn * Hn;

    // fork side streams off the captured origin stream
    cudaEventRecord(evRoot, 0);
    cudaStreamWaitEvent(s1, evRoot, 0);
    cudaStreamWaitEvent(s2, evRoot, 0);

    // s2: qkv + dense + out weight converts (qkv first — needed earliest)
    convert_f16_kernel<<<(int)(nq / (256 * 8)), 256, 0, s2>>>(w_qkv, (__half*)p_wq, nq);
    cudaEventRecord(evWQ, s2);
    convert_f16_kernel<<<(int)(nd / (256 * 8)), 256, 0, s2>>>(w_dense, (__half*)p_wd, nd);
    cudaEventRecord(evWD, s2);
    convert_f16_kernel<<<(int)(no / (256 * 8)), 256, 0, s2>>>(w_out, (__half*)p_wo, no);
    cudaEventRecord(evWO, s2);

    // s1: fc weight convert (fc gemm waits on LN)
    convert_f16_kernel<<<(int)(nf / (256 * 8)), 256, 0, s1>>>(w_fc, (__half*)p_wf, nf);

    // s0: double layernorm immediately (gates both branches)
    ln2_kernel<<<Mtok, 256>>>(hidden, ln_a_s, ln_a_b, ln_m_s, ln_m_b);
    cudaEventRecord(evLN, 0);

    // s1 branch: MLP fc + GELU (overlaps the whole attention branch on s0)
    cudaStreamWaitEvent(s1, evLN, 0);
    tc_gemm<1><<<dim3(FFn / BNg, Mtok / BMg), 256, SMEM_GEMM_TOTAL, s1>>>(
        (const __half*)p_m16, (const __half*)p_wf,
        nullptr, (__half*)p_f16, nullptr, nullptr, FFn, Hn);
    cudaEventRecord(evFC, s1);

    // s0 branch: attention chain (qkv gemm -> fp16, rope, attn, dense)
    cudaStreamWaitEvent(0, evWQ, 0);
    tc_gemm<4><<<dim3(QKVn / BNg, Mtok / BMg), 256, SMEM_GEMM_TOTAL>>>(
        (const __half*)p_a16, (const __half*)p_wq,
        nullptr, (__half*)p_qkvh, nullptr, nullptr, QKVn, Hn);
    {
        const long total = (long)Bn * Sn * NKVn * (Gn + 2) * HDn;
        rope_split_kernel<<<(int)((total + 255) / 256), 256>>>(sin_tab, cos_tab, pos_ids);
    }
    attn_hmma_kernel<<<dim3(Sn / BQ, NHn, Bn), 128, ATTN_SMEM_BYTES>>>(amask);

    cudaStreamWaitEvent(0, evWD, 0);
    tc_gemm<0><<<dim3(Hn / BNg, Mtok / BMg), 256, SMEM_GEMM_TOTAL>>>(
        (const __half*)p_c16, (const __half*)p_wd,
        (float*)p_ao, nullptr, nullptr, nullptr, Hn, Hn);

    // join: out gemm needs fc (s1), wo (s2), attn_out + hidden (s0)
    cudaStreamWaitEvent(0, evFC, 0);
    cudaStreamWaitEvent(0, evWO, 0);
    tc_gemm<2><<<dim3(Hn / BNg, Mtok / BMg), 256, SMEM_GEMM_TOTAL>>>(
        (const __half*)p_f16, (const __half*)p_wo,
        out, nullptr, hidden, (const float*)p_ao, Hn, FFn);
}